// round 3
// baseline (speedup 1.0000x reference)
#include <cuda_runtime.h>
#include <cuda_bf16.h>
#include <math.h>

#define B_   64
#define C_   192
#define C2_  384
#define HW_  3136            // 56*56
#define M_   (B_*HW_)        // 200704
#define LDHW (56*C2_)        // 21504 row stride in [*,H,W,2C] buffers

// ------------------------- scratch (device globals) -------------------------
__device__ float g_y0   [M_*C_];     // dwconv out, NHWC
__device__ float g_t1   [M_*C2_];    // lin1 out [x | z]
__device__ float g_xc   [M_*C2_];    // [idct1 result | outline]
__device__ float g_xd   [M_*C2_];    // second dct block output
__device__ float g_y3   [M_*C_];     // lin3 out
__device__ float g_yg   [M_*C_];     // LN * silu(z)
__device__ float g_femix[HW_*C_];
__device__ float g_mult1[HW_*C_];
__device__ float g_xmean[HW_*C2_];
__device__ float g_skft [HW_*C2_];
__device__ float g_mult2[HW_*C2_];
__device__ float g_cos  [HW_];       // cos[n*56+h]
__device__ float g_dval [HW_];       // wn^2+wm^2 at (n*56+m)

// ------------------------------- init --------------------------------------
__global__ void init_k(){
    int i = blockIdx.x*blockDim.x + threadIdx.x;
    if (i >= HW_) return;
    int n = i/56, h = i%56;
    const float PI = 3.14159265358979323846f;
    float xs = (h + 0.5f)/56.0f;
    float v = cosf((float)n * xs * PI) * sqrtf(2.0f/56.0f);
    if (n == 0) v *= 0.70710678118654752440f;
    g_cos[i] = v;
    float wn = PI*(float)n/56.0f, wm = PI*(float)h/56.0f;
    g_dval[i] = wn*wn + wm*wm;
}

// ------------------ femix = freq_embed + mean_b(outline) -------------------
__global__ void femix_k(const float* __restrict__ ot, const float* __restrict__ fe){
    int i = blockIdx.x*blockDim.x + threadIdx.x;     // float4 index
    if (i >= HW_*C_/4) return;
    const float4* o4 = (const float4*)ot;
    float4 s = make_float4(0,0,0,0);
    #pragma unroll 8
    for (int b = 0; b < B_; b++){
        float4 v = o4[(size_t)b*(HW_*C_/4) + i];
        s.x += v.x; s.y += v.y; s.z += v.z; s.w += v.w;
    }
    float4 f = ((const float4*)fe)[i];
    const float inv = 1.0f/B_;
    ((float4*)g_femix)[i] = make_float4(f.x+s.x*inv, f.y+s.y*inv, f.z+s.z*inv, f.w+s.w*inv);
}

// --------------------------- xmean = mean_b(xc) -----------------------------
__global__ void xmean_k(){
    int i = blockIdx.x*blockDim.x + threadIdx.x;     // float4 index
    if (i >= HW_*C2_/4) return;
    const float4* x4 = (const float4*)g_xc;
    float4 s = make_float4(0,0,0,0);
    #pragma unroll 8
    for (int b = 0; b < B_; b++){
        float4 v = x4[(size_t)b*(HW_*C2_/4) + i];
        s.x += v.x; s.y += v.y; s.z += v.z; s.w += v.w;
    }
    const float inv = 1.0f/B_;
    ((float4*)g_xmean)[i] = make_float4(s.x*inv, s.y*inv, s.z*inv, s.w*inv);
}

// ------------------- copy outline into xc[..., 192:384] --------------------
__global__ void copyol_k(const float* __restrict__ ot){
    int i = blockIdx.x*blockDim.x + threadIdx.x;     // float4 index, M_*48
    if (i >= M_*(C_/4)) return;
    int row = i/(C_/4), c4 = i - row*(C_/4);
    ((float4*)g_xc)[(size_t)row*(C2_/4) + (C_/4) + c4] = ((const float4*)ot)[i];
}

// -------------------- depthwise 3x3 conv, NCHW -> NHWC ---------------------
__global__ __launch_bounds__(256) void dwconv_k(const float* __restrict__ x,
        const float* __restrict__ wc, const float* __restrict__ bc){
    __shared__ float sm[32][33];
    __shared__ float wsm[32][9];
    __shared__ float bsm[32];
    int bid = blockIdx.x;
    int ct = bid % 6; int pt = (bid/6) % 98; int b = bid / 588;
    int c0 = ct*32, p0 = pt*32;
    int t = threadIdx.x;
    for (int i = t; i < 288; i += 256) wsm[i/9][i%9] = wc[(c0 + i/9)*9 + (i%9)];
    if (t < 32) bsm[t] = bc[c0+t];
    __syncthreads();
    int pi = t & 31, cq = t >> 5;
    int p = p0 + pi; int h = p/56, w = p - h*56;
    #pragma unroll
    for (int qq = 0; qq < 4; qq++){
        int cl = cq*4 + qq;
        const float* xp = x + ((size_t)b*C_ + c0 + cl)*HW_;
        float a = bsm[cl];
        #pragma unroll
        for (int dy = 0; dy < 3; dy++){
            int hh = h + dy - 1;
            if (hh < 0 || hh >= 56) continue;
            #pragma unroll
            for (int dx = 0; dx < 3; dx++){
                int ww = w + dx - 1;
                if (ww < 0 || ww >= 56) continue;
                a += xp[hh*56+ww]*wsm[cl][dy*3+dx];
            }
        }
        sm[cl][pi] = a;
    }
    __syncthreads();
    int ci = t & 31, pq = t >> 5;
    #pragma unroll
    for (int qq = 0; qq < 4; qq++){
        int pj = pq*4 + qq;
        g_y0[((size_t)b*HW_ + p0 + pj)*C_ + c0 + ci] = sm[ci][pj];
    }
}

// ------------------------------ SGEMM --------------------------------------
// C = A @ W^T (+bias). A:[M,K] rm, W:[N,K] rm. BM=128,BN=64,BK=16, 256 thr,
// 8x4 micro-tile. EPI 0: bias. EPI 1: exp(-relu(v)*dval[row]). EPI 2: NCHW.
template<int EPI>
__global__ __launch_bounds__(256) void gemm_k(
        const float* __restrict__ A, const float* __restrict__ Wm,
        const float* __restrict__ bias, float* __restrict__ Cout,
        int M, int N, int K, int ldc)
{
    __shared__ float As[16][132];
    __shared__ float Bs[16][64];
    int t = threadIdx.x;
    int row0 = blockIdx.y*128, col0 = blockIdx.x*64;
    int txi = t & 15, tyi = t >> 4;

    float acc[8][4];
    #pragma unroll
    for (int i = 0; i < 8; i++)
        #pragma unroll
        for (int j = 0; j < 4; j++) acc[i][j] = 0.f;

    int lr = t >> 2;            // 0..63
    int ac = (t & 3)*4;         // k offset 0,4,8,12
    const float4 z4 = make_float4(0,0,0,0);

    for (int k0 = 0; k0 < K; k0 += 16){
        int r0 = row0 + lr, r1 = row0 + lr + 64;
        float4 a0 = (r0 < M) ? *(const float4*)&A[(size_t)r0*K + k0 + ac] : z4;
        float4 a1 = (r1 < M) ? *(const float4*)&A[(size_t)r1*K + k0 + ac] : z4;
        float4 bv = *(const float4*)&Wm[(size_t)(col0 + lr)*K + k0 + ac];
        __syncthreads();
        As[ac+0][lr] = a0.x; As[ac+1][lr] = a0.y; As[ac+2][lr] = a0.z; As[ac+3][lr] = a0.w;
        As[ac+0][lr+64] = a1.x; As[ac+1][lr+64] = a1.y; As[ac+2][lr+64] = a1.z; As[ac+3][lr+64] = a1.w;
        Bs[ac+0][lr] = bv.x; Bs[ac+1][lr] = bv.y; Bs[ac+2][lr] = bv.z; Bs[ac+3][lr] = bv.w;
        __syncthreads();
        #pragma unroll
        for (int k = 0; k < 16; k++){
            float4 av0 = *(const float4*)&As[k][tyi*8];
            float4 av1 = *(const float4*)&As[k][tyi*8+4];
            float4 b0  = *(const float4*)&Bs[k][txi*4];
            float av[8] = {av0.x,av0.y,av0.z,av0.w,av1.x,av1.y,av1.z,av1.w};
            float bb[4] = {b0.x,b0.y,b0.z,b0.w};
            #pragma unroll
            for (int i = 0; i < 8; i++)
                #pragma unroll
                for (int j = 0; j < 4; j++) acc[i][j] += av[i]*bb[j];
        }
    }

    float bcol[4];
    #pragma unroll
    for (int j = 0; j < 4; j++) bcol[j] = bias[col0 + txi*4 + j];

    #pragma unroll
    for (int i = 0; i < 8; i++){
        int row = row0 + tyi*8 + i;
        if (row >= M) continue;
        #pragma unroll
        for (int j = 0; j < 4; j++){
            int col = col0 + txi*4 + j;
            float v = acc[i][j] + bcol[j];
            if (EPI == 0){
                Cout[(size_t)row*ldc + col] = v;
            } else if (EPI == 1){
                v = fmaxf(v, 0.f);
                Cout[(size_t)row*ldc + col] = expf(-v*g_dval[row]);
            } else {
                int b = row / HW_, p = row - b*HW_;
                Cout[((size_t)(b*N + col))*HW_ + p] = v;
            }
        }
    }
}

// ---------------- fused DCT2D * mult * IDCT2D per 56x56 slice --------------
// NOTE: the reference applies the cos matrix in the SAME orientation for the
// forward and "inverse" transforms (einsum labels renamed, contraction is
// always over the matrix's 2nd axis). So MM3==MM1 form, MM4==MM2 form.
// MODE 0: slice (b,c) on [B,H,W,2C] buffers (first C cols), mult1 [HW,C].
// MODE 1: interleaved slice (b,s,c') on [B,H,W,2C], mult2 [HW,2C].
__device__ __forceinline__ int coffj(int MODE, int j){
    return (MODE == 0) ? j*C2_ : ((j>>1)*C2_ + (j&1)*C_);
}
__device__ __forceinline__ int moffj(int MODE, int j){
    return (MODE == 0) ? j*C_ : ((j>>1)*C2_ + (j&1)*C_);
}

template<int MODE>
__global__ __launch_bounds__(256) void dct_k(const float* __restrict__ in,
                                             float* __restrict__ out,
                                             const float* __restrict__ mult)
{
    __shared__ float Sd[56][57];
    __shared__ float Td[56][57];
    __shared__ float Cs[56][57];
    int t = threadIdx.x;
    int id = blockIdx.x;
    size_t inBase, multBase; int mrow;
    if (MODE == 0){
        int b = id / C_, c = id - b*C_;
        inBase = (size_t)b*HW_*C2_ + c;
        multBase = (size_t)c; mrow = 56*C_;
    } else {
        int b = id / (2*C_); int r = id - b*2*C_;
        int s = r / C_, c = r - s*C_;
        inBase = (size_t)b*HW_*C2_ + (size_t)s*28*C2_ + c;
        multBase = (size_t)s*28*C2_ + c; mrow = 56*C2_;
    }
    for (int i = t; i < HW_; i += 256){
        int h = i/56, j = i - h*56;
        Cs[h][j] = g_cos[i];
        Sd[h][j] = in[inBase + (size_t)h*LDHW + coffj(MODE, j)];
    }
    __syncthreads();

    bool act = (t < 196);
    int tr = 0, tc = 0;
    if (act){ tr = (t/14)*4; tc = (t - (t/14)*14)*4; }
    float acc[4][4];

    // MM1: Td[n][w] = sum_h Cs[n][h]*Sd[h][w]
    if (act){
        #pragma unroll
        for (int i=0;i<4;i++){ acc[i][0]=0;acc[i][1]=0;acc[i][2]=0;acc[i][3]=0; }
        #pragma unroll 4
        for (int k = 0; k < 56; k++){
            float a[4], bb[4];
            #pragma unroll
            for (int i=0;i<4;i++) a[i] = Cs[tr+i][k];
            #pragma unroll
            for (int j=0;j<4;j++) bb[j] = Sd[k][tc+j];
            #pragma unroll
            for (int i=0;i<4;i++)
                #pragma unroll
                for (int j=0;j<4;j++) acc[i][j] += a[i]*bb[j];
        }
        #pragma unroll
        for (int i=0;i<4;i++)
            #pragma unroll
            for (int j=0;j<4;j++) Td[tr+i][tc+j] = acc[i][j];
    }
    __syncthreads();

    // MM2: Sd[n][m] = (sum_w Td[n][w]*Cs[m][w]) * mult
    if (act){
        #pragma unroll
        for (int i=0;i<4;i++){ acc[i][0]=0;acc[i][1]=0;acc[i][2]=0;acc[i][3]=0; }
        #pragma unroll 4
        for (int k = 0; k < 56; k++){
            float a[4], bb[4];
            #pragma unroll
            for (int i=0;i<4;i++) a[i] = Td[tr+i][k];
            #pragma unroll
            for (int j=0;j<4;j++) bb[j] = Cs[tc+j][k];
            #pragma unroll
            for (int i=0;i<4;i++)
                #pragma unroll
                for (int j=0;j<4;j++) acc[i][j] += a[i]*bb[j];
        }
        #pragma unroll
        for (int i=0;i<4;i++)
            #pragma unroll
            for (int j=0;j<4;j++){
                float mv = mult[multBase + (size_t)(tr+i)*mrow + moffj(MODE, tc+j)];
                Sd[tr+i][tc+j] = acc[i][j] * mv;
            }
    }
    __syncthreads();

    // MM3: Td[h][m] = sum_n Cs[h][n]*Sd[n][m]   (same orientation as MM1!)
    if (act){
        #pragma unroll
        for (int i=0;i<4;i++){ acc[i][0]=0;acc[i][1]=0;acc[i][2]=0;acc[i][3]=0; }
        #pragma unroll 4
        for (int k = 0; k < 56; k++){
            float a[4], bb[4];
            #pragma unroll
            for (int i=0;i<4;i++) a[i] = Cs[tr+i][k];
            #pragma unroll
            for (int j=0;j<4;j++) bb[j] = Sd[k][tc+j];
            #pragma unroll
            for (int i=0;i<4;i++)
                #pragma unroll
                for (int j=0;j<4;j++) acc[i][j] += a[i]*bb[j];
        }
        #pragma unroll
        for (int i=0;i<4;i++)
            #pragma unroll
            for (int j=0;j<4;j++) Td[tr+i][tc+j] = acc[i][j];
    }
    __syncthreads();

    // MM4: out[h][w] = sum_m Td[h][m]*Cs[w][m]   (same orientation as MM2!)
    if (act){
        #pragma unroll
        for (int i=0;i<4;i++){ acc[i][0]=0;acc[i][1]=0;acc[i][2]=0;acc[i][3]=0; }
        #pragma unroll 4
        for (int k = 0; k < 56; k++){
            float a[4], bb[4];
            #pragma unroll
            for (int i=0;i<4;i++) a[i] = Td[tr+i][k];
            #pragma unroll
            for (int j=0;j<4;j++) bb[j] = Cs[tc+j][k];
            #pragma unroll
            for (int i=0;i<4;i++)
                #pragma unroll
                for (int j=0;j<4;j++) acc[i][j] += a[i]*bb[j];
        }
        #pragma unroll
        for (int i=0;i<4;i++)
            #pragma unroll
            for (int j=0;j<4;j++)
                out[inBase + (size_t)(tr+i)*LDHW + coffj(MODE, tc+j)] = acc[i][j];
    }
}

// ------------------------- LayerNorm * silu(z) ------------------------------
__global__ __launch_bounds__(256) void lngate_k(const float* __restrict__ gam,
                                                const float* __restrict__ bet)
{
    int gw = (blockIdx.x*blockDim.x + threadIdx.x) >> 5;   // row
    if (gw >= M_) return;
    int lane = threadIdx.x & 31;
    const float* xr = g_y3 + (size_t)gw*C_;
    float v[6];
    float s = 0.f;
    #pragma unroll
    for (int i = 0; i < 6; i++){ v[i] = xr[lane + 32*i]; s += v[i]; }
    #pragma unroll
    for (int o = 16; o > 0; o >>= 1) s += __shfl_xor_sync(0xffffffffu, s, o);
    float mu = s * (1.0f/C_);
    float q = 0.f;
    #pragma unroll
    for (int i = 0; i < 6; i++){ float d = v[i]-mu; q += d*d; }
    #pragma unroll
    for (int o = 16; o > 0; o >>= 1) q += __shfl_xor_sync(0xffffffffu, q, o);
    float rstd = rsqrtf(q*(1.0f/C_) + 1e-5f);
    const float* zr = g_t1 + (size_t)gw*C2_ + C_;
    float* orow = g_yg + (size_t)gw*C_;
    #pragma unroll
    for (int i = 0; i < 6; i++){
        int c = lane + 32*i;
        float zz = zr[c];
        float sil = zz / (1.0f + expf(-zz));
        orow[c] = ((v[i]-mu)*rstd*gam[c] + bet[c]) * sil;
    }
}

// --------------------------------- launch ----------------------------------
extern "C" void kernel_launch(void* const* d_in, const int* in_sizes, int n_in,
                              void* d_out, int out_size)
{
    const float* x        = (const float*)d_in[0];
    const float* fe       = (const float*)d_in[1];
    const float* ot       = (const float*)d_in[2];
    const float* dw_w     = (const float*)d_in[3];
    const float* dw_b     = (const float*)d_in[4];
    const float* lin_w    = (const float*)d_in[5];
    const float* lin_b    = (const float*)d_in[6];
    const float* tok_w    = (const float*)d_in[7];
    const float* tok_b    = (const float*)d_in[8];
    const float* lin2_w   = (const float*)d_in[9];
    const float* lin2_b   = (const float*)d_in[10];
    const float* tok2_w   = (const float*)d_in[11];
    const float* tok2_b   = (const float*)d_in[12];
    const float* lin3_w   = (const float*)d_in[13];
    const float* lin3_b   = (const float*)d_in[14];
    const float* norm_g   = (const float*)d_in[15];
    const float* norm_b   = (const float*)d_in[16];
    const float* out_w    = (const float*)d_in[17];
    const float* out_b    = (const float*)d_in[18];
    float* out = (float*)d_out;

    float *t1, *xc, *xd, *y0, *femix, *mult1, *xmean, *skft, *mult2;
    cudaGetSymbolAddress((void**)&y0,    g_y0);
    cudaGetSymbolAddress((void**)&t1,    g_t1);
    cudaGetSymbolAddress((void**)&xc,    g_xc);
    cudaGetSymbolAddress((void**)&xd,    g_xd);
    cudaGetSymbolAddress((void**)&femix, g_femix);
    cudaGetSymbolAddress((void**)&mult1, g_mult1);
    cudaGetSymbolAddress((void**)&xmean, g_xmean);
    cudaGetSymbolAddress((void**)&skft,  g_skft);
    cudaGetSymbolAddress((void**)&mult2, g_mult2);
    float *y3, *yg;
    cudaGetSymbolAddress((void**)&y3,    g_y3);
    cudaGetSymbolAddress((void**)&yg,    g_yg);

    init_k<<<(HW_+255)/256, 256>>>();
    dwconv_k<<<64*6*98, 256>>>(x, dw_w, dw_b);
    femix_k<<<(HW_*C_/4 + 255)/256, 256>>>(ot, fe);
    copyol_k<<<(M_*(C_/4) + 255)/256, 256>>>(ot);

    // mult1 = exp(-relu(femix @ tok_w^T + tok_b) * dval)
    gemm_k<1><<<dim3(C_/64, (HW_+127)/128), 256>>>(femix, tok_w, tok_b, mult1,
                                                   HW_, C_, C_, C_);
    // t1 = y0 @ lin_w^T + lin_b
    gemm_k<0><<<dim3(C2_/64, (M_+127)/128), 256>>>(y0, lin_w, lin_b, t1,
                                                   M_, C2_, C_, C2_);
    // xc[:, :C] = "idct2"(dct2(x) * mult1)
    dct_k<0><<<B_*C_, 256>>>(t1, xc, mult1);

    xmean_k<<<(HW_*C2_/4 + 255)/256, 256>>>();
    // skft = xmean @ lin2_w^T + lin2_b
    gemm_k<0><<<dim3(C2_/64, (HW_+127)/128), 256>>>(xmean, lin2_w, lin2_b, skft,
                                                    HW_, C2_, C2_, C2_);
    // mult2 = exp(-relu(skft @ tok2_w^T + tok2_b) * dval)
    gemm_k<1><<<dim3(C2_/64, (HW_+127)/128), 256>>>(skft, tok2_w, tok2_b, mult2,
                                                    HW_, C2_, C2_, C2_);
    // xd = interleaved "idct2"(dct2(xc) * mult2)
    dct_k<1><<<B_*2*C_, 256>>>(xc, xd, mult2);

    // y3 = xd @ lin3_w^T + lin3_b
    gemm_k<0><<<dim3(C_/64, (M_+127)/128), 256>>>(xd, lin3_w, lin3_b, y3,
                                                  M_, C_, C2_, C_);
    // yg = LN(y3) * silu(z)
    lngate_k<<<(M_*32 + 255)/256, 256>>>(norm_g, norm_b);
    // out = yg @ out_w^T + out_b, stored NCHW
    gemm_k<2><<<dim3(C_/64, (M_+127)/128), 256>>>(yg, out_w, out_b, out,
                                                  M_, C_, C_, C_);
}

// round 4
// speedup vs baseline: 1.2362x; 1.2362x over previous
#include <cuda_runtime.h>
#include <cuda_bf16.h>
#include <cstdint>
#include <math.h>

#define B_   64
#define C_   192
#define C2_  384
#define HW_  3136            // 56*56
#define M_   (B_*HW_)        // 200704
#define LDHW (56*C2_)        // row stride (h) in [*,H,W,2C] buffers

// ------------------------- scratch (device globals) -------------------------
__device__ float g_y0    [M_*C_];     // dwconv out, NHWC
__device__ float g_t1    [M_*C2_];    // lin1 out [x | z]
__device__ float g_xc    [M_*C2_];    // idct1 result in first C cols
__device__ float g_xd    [M_*C2_];    // second dct block output
__device__ float g_y3    [M_*C_];     // lin3 out
__device__ float g_yg    [M_*C_];     // LN * silu(z)
__device__ float g_femix [HW_*C_];
__device__ float g_otmean[HW_*C_];
__device__ float g_mult1 [HW_*C_];
__device__ float g_xmean [HW_*C2_];
__device__ float g_skft  [HW_*C2_];
__device__ float g_mult2 [HW_*C2_];
__device__ float g_cos   [HW_];       // cos[n*56+h]
__device__ float g_dval  [HW_];       // wn^2+wm^2 at (n*56+m)

// ------------------------------- init --------------------------------------
__global__ void init_k(){
    int i = blockIdx.x*blockDim.x + threadIdx.x;
    if (i >= HW_) return;
    int n = i/56, h = i%56;
    const float PI = 3.14159265358979323846f;
    float xs = (h + 0.5f)/56.0f;
    float v = cosf((float)n * xs * PI) * sqrtf(2.0f/56.0f);
    if (n == 0) v *= 0.70710678118654752440f;
    g_cos[i] = v;
    float wn = PI*(float)n/56.0f, wm = PI*(float)h/56.0f;
    g_dval[i] = wn*wn + wm*wm;
}

// ---------- femix = freq_embed + mean_b(outline); also store otmean --------
__global__ void femix_k(const float* __restrict__ ot, const float* __restrict__ fe){
    int i = blockIdx.x*blockDim.x + threadIdx.x;     // float4 index
    if (i >= HW_*C_/4) return;
    const float4* o4 = (const float4*)ot;
    float4 s = make_float4(0,0,0,0);
    #pragma unroll 8
    for (int b = 0; b < B_; b++){
        float4 v = o4[(size_t)b*(HW_*C_/4) + i];
        s.x += v.x; s.y += v.y; s.z += v.z; s.w += v.w;
    }
    const float inv = 1.0f/B_;
    float4 m = make_float4(s.x*inv, s.y*inv, s.z*inv, s.w*inv);
    ((float4*)g_otmean)[i] = m;
    float4 f = ((const float4*)fe)[i];
    ((float4*)g_femix)[i] = make_float4(f.x+m.x, f.y+m.y, f.z+m.z, f.w+m.w);
}

// -------- xmean: first half = mean_b(xc[:, :C]), second half = otmean -------
__global__ void xmean_k(){
    int i = blockIdx.x*blockDim.x + threadIdx.x;     // float4 index over HW*C/4
    if (i >= HW_*C_/4) return;
    int row = i/(C_/4), c4 = i - row*(C_/4);
    const float4* x4 = (const float4*)g_xc;
    float4 s = make_float4(0,0,0,0);
    #pragma unroll 8
    for (int b = 0; b < B_; b++){
        float4 v = x4[(size_t)(b*HW_ + row)*(C2_/4) + c4];
        s.x += v.x; s.y += v.y; s.z += v.z; s.w += v.w;
    }
    const float inv = 1.0f/B_;
    ((float4*)g_xmean)[(size_t)row*(C2_/4) + c4] =
        make_float4(s.x*inv, s.y*inv, s.z*inv, s.w*inv);
    ((float4*)g_xmean)[(size_t)row*(C2_/4) + (C_/4) + c4] = ((const float4*)g_otmean)[i];
}

// -------------------- depthwise 3x3 conv, NCHW -> NHWC ---------------------
__global__ __launch_bounds__(256) void dwconv_k(const float* __restrict__ x,
        const float* __restrict__ wc, const float* __restrict__ bc){
    __shared__ float sm[32][33];
    __shared__ float wsm[32][9];
    __shared__ float bsm[32];
    int bid = blockIdx.x;
    int ct = bid % 6; int pt = (bid/6) % 98; int b = bid / 588;
    int c0 = ct*32, p0 = pt*32;
    int t = threadIdx.x;
    for (int i = t; i < 288; i += 256) wsm[i/9][i%9] = wc[(c0 + i/9)*9 + (i%9)];
    if (t < 32) bsm[t] = bc[c0+t];
    __syncthreads();
    int pi = t & 31, cq = t >> 5;
    int p = p0 + pi; int h = p/56, w = p - h*56;
    #pragma unroll
    for (int qq = 0; qq < 4; qq++){
        int cl = cq*4 + qq;
        const float* xp = x + ((size_t)b*C_ + c0 + cl)*HW_;
        float a = bsm[cl];
        #pragma unroll
        for (int dy = 0; dy < 3; dy++){
            int hh = h + dy - 1;
            if (hh < 0 || hh >= 56) continue;
            #pragma unroll
            for (int dx = 0; dx < 3; dx++){
                int ww = w + dx - 1;
                if (ww < 0 || ww >= 56) continue;
                a += xp[hh*56+ww]*wsm[cl][dy*3+dx];
            }
        }
        sm[cl][pi] = a;
    }
    __syncthreads();
    int ci = t & 31, pq = t >> 5;
    #pragma unroll
    for (int qq = 0; qq < 4; qq++){
        int pj = pq*4 + qq;
        g_y0[((size_t)b*HW_ + p0 + pj)*C_ + c0 + ci] = sm[ci][pj];
    }
}

// ------------------ legacy SIMT SGEMM (small HW_ GEMMs only) ---------------
template<int EPI>
__global__ __launch_bounds__(256) void gemm_k(
        const float* __restrict__ A, const float* __restrict__ Wm,
        const float* __restrict__ bias, float* __restrict__ Cout,
        int M, int N, int K, int ldc)
{
    __shared__ float As[16][132];
    __shared__ float Bs[16][64];
    int t = threadIdx.x;
    int row0 = blockIdx.y*128, col0 = blockIdx.x*64;
    int txi = t & 15, tyi = t >> 4;

    float acc[8][4];
    #pragma unroll
    for (int i = 0; i < 8; i++)
        #pragma unroll
        for (int j = 0; j < 4; j++) acc[i][j] = 0.f;

    int lr = t >> 2;
    int ac = (t & 3)*4;
    const float4 z4 = make_float4(0,0,0,0);

    for (int k0 = 0; k0 < K; k0 += 16){
        int r0 = row0 + lr, r1 = row0 + lr + 64;
        float4 a0 = (r0 < M) ? *(const float4*)&A[(size_t)r0*K + k0 + ac] : z4;
        float4 a1 = (r1 < M) ? *(const float4*)&A[(size_t)r1*K + k0 + ac] : z4;
        float4 bv = *(const float4*)&Wm[(size_t)(col0 + lr)*K + k0 + ac];
        __syncthreads();
        As[ac+0][lr] = a0.x; As[ac+1][lr] = a0.y; As[ac+2][lr] = a0.z; As[ac+3][lr] = a0.w;
        As[ac+0][lr+64] = a1.x; As[ac+1][lr+64] = a1.y; As[ac+2][lr+64] = a1.z; As[ac+3][lr+64] = a1.w;
        Bs[ac+0][lr] = bv.x; Bs[ac+1][lr] = bv.y; Bs[ac+2][lr] = bv.z; Bs[ac+3][lr] = bv.w;
        __syncthreads();
        #pragma unroll
        for (int k = 0; k < 16; k++){
            float4 av0 = *(const float4*)&As[k][tyi*8];
            float4 av1 = *(const float4*)&As[k][tyi*8+4];
            float4 b0  = *(const float4*)&Bs[k][txi*4];
            float av[8] = {av0.x,av0.y,av0.z,av0.w,av1.x,av1.y,av1.z,av1.w};
            float bb[4] = {b0.x,b0.y,b0.z,b0.w};
            #pragma unroll
            for (int i = 0; i < 8; i++)
                #pragma unroll
                for (int j = 0; j < 4; j++) acc[i][j] += av[i]*bb[j];
        }
    }

    float bcol[4];
    #pragma unroll
    for (int j = 0; j < 4; j++) bcol[j] = bias[col0 + txi*4 + j];

    #pragma unroll
    for (int i = 0; i < 8; i++){
        int row = row0 + tyi*8 + i;
        if (row >= M) continue;
        #pragma unroll
        for (int j = 0; j < 4; j++){
            int col = col0 + txi*4 + j;
            float v = acc[i][j] + bcol[j];
            if (EPI == 0){
                Cout[(size_t)row*ldc + col] = v;
            } else {
                v = fmaxf(v, 0.f);
                Cout[(size_t)row*ldc + col] = expf(-v*g_dval[row]);
            }
        }
    }
}

// ------------------------ tf32 tensor-core GEMM ----------------------------
// C = A @ W^T (+bias). BM=128, BN=192, BK=16, 8 warps (4x2), warp tile 32x96.
// Requires M%128==0, N%192==0, K%16==0. EPI 0: bias. EPI 2: NCHW scatter.
__device__ __forceinline__ float to_tf32(float x){
    uint32_t u; asm("cvt.rna.tf32.f32 %0, %1;" : "=r"(u) : "f"(x));
    return __uint_as_float(u);
}
__device__ __forceinline__ void mma_tf32(float c[4], const uint32_t a[4], const uint32_t b[2]){
    asm volatile("mma.sync.aligned.m16n8k8.row.col.f32.tf32.tf32.f32 "
        "{%0,%1,%2,%3}, {%4,%5,%6,%7}, {%8,%9}, {%0,%1,%2,%3};"
        : "+f"(c[0]), "+f"(c[1]), "+f"(c[2]), "+f"(c[3])
        : "r"(a[0]), "r"(a[1]), "r"(a[2]), "r"(a[3]), "r"(b[0]), "r"(b[1]));
}

template<int EPI>
__global__ __launch_bounds__(256) void tgemm_k(
        const float* __restrict__ A, const float* __restrict__ Wm,
        const float* __restrict__ bias, float* __restrict__ Cout,
        int N, int K, int ldc)
{
    __shared__ float As[2][16][136];   // 136 % 32 == 8 -> conflict-free frags
    __shared__ float Bs[2][16][200];   // 200 % 32 == 8
    const int t = threadIdx.x;
    const int lane = t & 31, warp = t >> 5;
    const int gid = lane >> 2, tig = lane & 3;
    const int wm = warp & 3, wn = warp >> 2;
    const int m0 = wm*32, n0 = wn*96;
    const int row0 = blockIdx.y*128, col0 = blockIdx.x*192;

    float acc[2][12][4];
    #pragma unroll
    for (int mt = 0; mt < 2; mt++)
        #pragma unroll
        for (int nt = 0; nt < 12; nt++)
            #pragma unroll
            for (int q = 0; q < 4; q++) acc[mt][nt][q] = 0.f;

    const int arow = t >> 1, ak = (t & 1)*8;
    const float* Ag = A + (size_t)(row0 + arow)*K + ak;
    int   brow[3], bk[3];
    const float* Bg[3];
    #pragma unroll
    for (int r = 0; r < 3; r++){
        int idx = t + r*256;
        brow[r] = idx >> 2; bk[r] = (idx & 3)*4;
        Bg[r] = Wm + (size_t)(col0 + brow[r])*K + bk[r];
    }

    float4 pa0, pa1, pb[3];
    pa0 = *(const float4*)(Ag);
    pa1 = *(const float4*)(Ag + 4);
    #pragma unroll
    for (int r = 0; r < 3; r++) pb[r] = *(const float4*)(Bg[r]);

    // stash stage 0
    {
        As[0][ak+0][arow] = to_tf32(pa0.x); As[0][ak+1][arow] = to_tf32(pa0.y);
        As[0][ak+2][arow] = to_tf32(pa0.z); As[0][ak+3][arow] = to_tf32(pa0.w);
        As[0][ak+4][arow] = to_tf32(pa1.x); As[0][ak+5][arow] = to_tf32(pa1.y);
        As[0][ak+6][arow] = to_tf32(pa1.z); As[0][ak+7][arow] = to_tf32(pa1.w);
        #pragma unroll
        for (int r = 0; r < 3; r++){
            Bs[0][bk[r]+0][brow[r]] = to_tf32(pb[r].x);
            Bs[0][bk[r]+1][brow[r]] = to_tf32(pb[r].y);
            Bs[0][bk[r]+2][brow[r]] = to_tf32(pb[r].z);
            Bs[0][bk[r]+3][brow[r]] = to_tf32(pb[r].w);
        }
    }
    __syncthreads();

    const int nIter = K >> 4;
    int s = 0;
    for (int it = 0; it < nIter; it++){
        if (it + 1 < nIter){
            int k0 = (it+1) << 4;
            pa0 = *(const float4*)(Ag + k0);
            pa1 = *(const float4*)(Ag + k0 + 4);
            #pragma unroll
            for (int r = 0; r < 3; r++) pb[r] = *(const float4*)(Bg[r] + k0);
        }
        #pragma unroll
        for (int ks = 0; ks < 16; ks += 8){
            uint32_t af[2][4];
            #pragma unroll
            for (int mt = 0; mt < 2; mt++){
                int mm = m0 + mt*16 + gid;
                af[mt][0] = __float_as_uint(As[s][ks+tig  ][mm]);
                af[mt][1] = __float_as_uint(As[s][ks+tig  ][mm+8]);
                af[mt][2] = __float_as_uint(As[s][ks+tig+4][mm]);
                af[mt][3] = __float_as_uint(As[s][ks+tig+4][mm+8]);
            }
            uint32_t bf[12][2];
            #pragma unroll
            for (int nt = 0; nt < 12; nt++){
                int nn = n0 + nt*8 + gid;
                bf[nt][0] = __float_as_uint(Bs[s][ks+tig  ][nn]);
                bf[nt][1] = __float_as_uint(Bs[s][ks+tig+4][nn]);
            }
            #pragma unroll
            for (int mt = 0; mt < 2; mt++)
                #pragma unroll
                for (int nt = 0; nt < 12; nt++)
                    mma_tf32(acc[mt][nt], af[mt], bf[nt]);
        }
        if (it + 1 < nIter){
            int sn = s ^ 1;
            As[sn][ak+0][arow] = to_tf32(pa0.x); As[sn][ak+1][arow] = to_tf32(pa0.y);
            As[sn][ak+2][arow] = to_tf32(pa0.z); As[sn][ak+3][arow] = to_tf32(pa0.w);
            As[sn][ak+4][arow] = to_tf32(pa1.x); As[sn][ak+5][arow] = to_tf32(pa1.y);
            As[sn][ak+6][arow] = to_tf32(pa1.z); As[sn][ak+7][arow] = to_tf32(pa1.w);
            #pragma unroll
            for (int r = 0; r < 3; r++){
                Bs[sn][bk[r]+0][brow[r]] = to_tf32(pb[r].x);
                Bs[sn][bk[r]+1][brow[r]] = to_tf32(pb[r].y);
                Bs[sn][bk[r]+2][brow[r]] = to_tf32(pb[r].z);
                Bs[sn][bk[r]+3][brow[r]] = to_tf32(pb[r].w);
            }
            __syncthreads();
            s = sn;
        }
    }

    // epilogue
    #pragma unroll
    for (int mt = 0; mt < 2; mt++){
        #pragma unroll
        for (int nt = 0; nt < 12; nt++){
            int r0 = row0 + m0 + mt*16 + gid;
            int cc = col0 + n0 + nt*8 + tig*2;
            float b0v = bias[cc], b1v = bias[cc+1];
            float v00 = acc[mt][nt][0] + b0v, v01 = acc[mt][nt][1] + b1v;
            float v10 = acc[mt][nt][2] + b0v, v11 = acc[mt][nt][3] + b1v;
            if (EPI == 0){
                *(float2*)&Cout[(size_t)r0*ldc + cc]     = make_float2(v00, v01);
                *(float2*)&Cout[(size_t)(r0+8)*ldc + cc] = make_float2(v10, v11);
            } else {
                int b0i = r0 / HW_,  p0i = r0 - b0i*HW_;
                int b1i = (r0+8) / HW_, p1i = (r0+8) - b1i*HW_;
                Cout[((size_t)(b0i*N + cc  ))*HW_ + p0i] = v00;
                Cout[((size_t)(b0i*N + cc+1))*HW_ + p0i] = v01;
                Cout[((size_t)(b1i*N + cc  ))*HW_ + p1i] = v10;
                Cout[((size_t)(b1i*N + cc+1))*HW_ + p1i] = v11;
            }
        }
    }
}

// ---------------- fused DCT2D * mult * IDCT2D per 56x56 slice --------------
// Reference applies the cos matrix in the SAME orientation in all 4 passes.
// MODE 0: slice (b,c), reads t1 first-C cols, writes xc first-C cols.
// MODE 1: interleaved slice (b,s,c'); col j -> (spatial 28s+(j>>1), half j&1);
//         odd half read directly from outline tensor.
#define DSTR 56   // row stride in floats (224B, 16B-aligned)
template<int MODE>
__global__ __launch_bounds__(224) void dct_k(const float* __restrict__ in,
                                             const float* __restrict__ otl,
                                             float* __restrict__ out,
                                             const float* __restrict__ mult)
{
    extern __shared__ float sh[];
    float* Sd = sh;              // [56][56]
    float* Td = sh + 3136;
    float* Cs = sh + 6272;       // Cs[n][h]
    float* Ct = sh + 9408;       // Ct[h][n] = Cs[n][h]
    const int t = threadIdx.x;
    const int id = blockIdx.x;

    size_t inBase, otBase = 0, multBase; int mrow;
    if (MODE == 0){
        int b = id / C_, c = id - b*C_;
        inBase = (size_t)b*HW_*C2_ + c;
        multBase = (size_t)c; mrow = 56*C_;
    } else {
        int b = id / (2*C_); int r = id - b*2*C_;
        int sH = r / C_, c = r - sH*C_;
        inBase = (size_t)b*HW_*C2_ + (size_t)sH*28*C2_ + c;
        otBase = (size_t)b*HW_*C_ + (size_t)sH*28*C_ + c;
        multBase = (size_t)sH*28*C2_ + c; mrow = 56*C2_;
    }

    for (int i = t; i < HW_; i += 224){
        int r = i/56, q = i - r*56;
        float cv = g_cos[i];
        Cs[r*DSTR + q] = cv;
        Ct[q*DSTR + r] = cv;
        float v;
        if (MODE == 0){
            v = in[inBase + (size_t)r*LDHW + (size_t)q*C2_];
        } else {
            int jj = q >> 1;
            if (q & 1) v = otl[otBase + (size_t)r*(56*C_) + (size_t)jj*C_];
            else       v = in[inBase + (size_t)r*LDHW + (size_t)jj*C2_];
        }
        Sd[r*DSTR + q] = v;
    }
    __syncthreads();

    const bool act = (t < 196);
    int tr = 0, tc = 0;
    if (act){ tr = (t/14)*4; tc = (t - (t/14)*14)*4; }
    float acc[4][4];

    // generic 4x4 tile of  acc = Arow(tr) x Bmat(:, tc)   (contract over 56)
    auto mm56 = [&](const float* Arow, const float* Bmat){
        #pragma unroll
        for (int i = 0; i < 4; i++){ acc[i][0]=0;acc[i][1]=0;acc[i][2]=0;acc[i][3]=0; }
        for (int k4 = 0; k4 < 56; k4 += 4){
            float av[4][4], bv[4][4];
            #pragma unroll
            for (int i = 0; i < 4; i++)
                *(float4*)av[i] = *(const float4*)&Arow[(tr+i)*DSTR + k4];
            #pragma unroll
            for (int kk = 0; kk < 4; kk++)
                *(float4*)bv[kk] = *(const float4*)&Bmat[(k4+kk)*DSTR + tc];
            #pragma unroll
            for (int kk = 0; kk < 4; kk++)
                #pragma unroll
                for (int i = 0; i < 4; i++)
                    #pragma unroll
                    for (int j = 0; j < 4; j++)
                        acc[i][j] += av[i][kk]*bv[kk][j];
        }
    };

    // MM1: Td = Cs x Sd
    if (act){
        mm56(Cs, Sd);
        #pragma unroll
        for (int i = 0; i < 4; i++) *(float4*)&Td[(tr+i)*DSTR + tc] = *(float4*)acc[i];
    }
    __syncthreads();
    // MM2: Sd = (Td x Cs^T) * mult    (b operand = Ct rows)
    if (act){
        mm56(Td, Ct);
        #pragma unroll
        for (int i = 0; i < 4; i++)
            #pragma unroll
            for (int j = 0; j < 4; j++){
                float mv = mult[multBase + (size_t)(tr+i)*mrow +
                                ((MODE==0) ? (size_t)(tc+j)*C_
                                           : (size_t)((tc+j)>>1)*C2_ + (size_t)((tc+j)&1)*C_)];
                acc[i][j] *= mv;
            }
        #pragma unroll
        for (int i = 0; i < 4; i++) *(float4*)&Sd[(tr+i)*DSTR + tc] = *(float4*)acc[i];
    }
    __syncthreads();
    // MM3: Td = Cs x Sd
    if (act){
        mm56(Cs, Sd);
        #pragma unroll
        for (int i = 0; i < 4; i++) *(float4*)&Td[(tr+i)*DSTR + tc] = *(float4*)acc[i];
    }
    __syncthreads();
    // MM4: out = Td x Cs^T
    if (act){
        mm56(Td, Ct);
        #pragma unroll
        for (int i = 0; i < 4; i++)
            #pragma unroll
            for (int j = 0; j < 4; j++){
                size_t off = (MODE==0) ? (size_t)(tc+j)*C2_
                                       : (size_t)((tc+j)>>1)*C2_ + (size_t)((tc+j)&1)*C_;
                out[inBase + (size_t)(tr+i)*LDHW + off] = acc[i][j];
            }
    }
}

// ------------------------- LayerNorm * silu(z) ------------------------------
__global__ __launch_bounds__(256) void lngate_k(const float* __restrict__ gam,
                                                const float* __restrict__ bet)
{
    int gw = (blockIdx.x*blockDim.x + threadIdx.x) >> 5;
    if (gw >= M_) return;
    int lane = threadIdx.x & 31;
    const float* xr = g_y3 + (size_t)gw*C_;
    float v[6];
    float s = 0.f;
    #pragma unroll
    for (int i = 0; i < 6; i++){ v[i] = xr[lane + 32*i]; s += v[i]; }
    #pragma unroll
    for (int o = 16; o > 0; o >>= 1) s += __shfl_xor_sync(0xffffffffu, s, o);
    float mu = s * (1.0f/C_);
    float q = 0.f;
    #pragma unroll
    for (int i = 0; i < 6; i++){ float d = v[i]-mu; q += d*d; }
    #pragma unroll
    for (int o = 16; o > 0; o >>= 1) q += __shfl_xor_sync(0xffffffffu, q, o);
    float rstd = rsqrtf(q*(1.0f/C_) + 1e-5f);
    const float* zr = g_t1 + (size_t)gw*C2_ + C_;
    float* orow = g_yg + (size_t)gw*C_;
    #pragma unroll
    for (int i = 0; i < 6; i++){
        int c = lane + 32*i;
        float zz = zr[c];
        float sil = zz / (1.0f + expf(-zz));
        orow[c] = ((v[i]-mu)*rstd*gam[c] + bet[c]) * sil;
    }
}

// --------------------------------- launch ----------------------------------
extern "C" void kernel_launch(void* const* d_in, const int* in_sizes, int n_in,
                              void* d_out, int out_size)
{
    const float* x        = (const float*)d_in[0];
    const float* fe       = (const float*)d_in[1];
    const float* ot       = (const float*)d_in[2];
    const float* dw_w     = (const float*)d_in[3];
    const float* dw_b     = (const float*)d_in[4];
    const float* lin_w    = (const float*)d_in[5];
    const float* lin_b    = (const float*)d_in[6];
    const float* tok_w    = (const float*)d_in[7];
    const float* tok_b    = (const float*)d_in[8];
    const float* lin2_w   = (const float*)d_in[9];
    const float* lin2_b   = (const float*)d_in[10];
    const float* tok2_w   = (const float*)d_in[11];
    const float* tok2_b   = (const float*)d_in[12];
    const float* lin3_w   = (const float*)d_in[13];
    const float* lin3_b   = (const float*)d_in[14];
    const float* norm_g   = (const float*)d_in[15];
    const float* norm_b   = (const float*)d_in[16];
    const float* out_w    = (const float*)d_in[17];
    const float* out_b    = (const float*)d_in[18];
    float* out = (float*)d_out;

    float *y0, *t1, *xc, *xd, *femix, *mult1, *xmean, *skft, *mult2, *y3, *yg;
    cudaGetSymbolAddress((void**)&y0,    g_y0);
    cudaGetSymbolAddress((void**)&t1,    g_t1);
    cudaGetSymbolAddress((void**)&xc,    g_xc);
    cudaGetSymbolAddress((void**)&xd,    g_xd);
    cudaGetSymbolAddress((void**)&femix, g_femix);
    cudaGetSymbolAddress((void**)&mult1, g_mult1);
    cudaGetSymbolAddress((void**)&xmean, g_xmean);
    cudaGetSymbolAddress((void**)&skft,  g_skft);
    cudaGetSymbolAddress((void**)&mult2, g_mult2);
    cudaGetSymbolAddress((void**)&y3,    g_y3);
    cudaGetSymbolAddress((void**)&yg,    g_yg);

    const int DCT_SMEM = 4*3136*4 + 256;   // 50432 B
    cudaFuncSetAttribute(dct_k<0>, cudaFuncAttributeMaxDynamicSharedMemorySize, DCT_SMEM);
    cudaFuncSetAttribute(dct_k<1>, cudaFuncAttributeMaxDynamicSharedMemorySize, DCT_SMEM);

    init_k<<<(HW_+255)/256, 256>>>();
    dwconv_k<<<64*6*98, 256>>>(x, dw_w, dw_b);
    femix_k<<<(HW_*C_/4 + 255)/256, 256>>>(ot, fe);

    // mult1 = exp(-relu(femix @ tok_w^T + tok_b) * dval)
    gemm_k<1><<<dim3(C_/64, (HW_+127)/128), 256>>>(femix, tok_w, tok_b, mult1,
                                                   HW_, C_, C_, C_);
    // t1 = y0 @ lin_w^T + lin_b   (tf32 TC)
    tgemm_k<0><<<dim3(C2_/192, M_/128), 256>>>(y0, lin_w, lin_b, t1, C2_, C_, C2_);
    // xc[:, :C] = "idct2"(dct2(x) * mult1)
    dct_k<0><<<B_*C_, 224, DCT_SMEM>>>(t1, nullptr, xc, mult1);

    xmean_k<<<(HW_*C_/4 + 255)/256, 256>>>();
    // skft = xmean @ lin2_w^T + lin2_b
    gemm_k<0><<<dim3(C2_/64, (HW_+127)/128), 256>>>(xmean, lin2_w, lin2_b, skft,
                                                    HW_, C2_, C2_, C2_);
    // mult2 = exp(-relu(skft @ tok2_w^T + tok2_b) * dval)
    gemm_k<1><<<dim3(C2_/64, (HW_+127)/128), 256>>>(skft, tok2_w, tok2_b, mult2,
                                                    HW_, C2_, C2_, C2_);
    // xd = interleaved "idct2"(dct2([xc | outline]) * mult2)
    dct_k<1><<<B_*2*C_, 224, DCT_SMEM>>>(xc, ot, xd, mult2);

    // y3 = xd @ lin3_w^T + lin3_b   (tf32 TC)
    tgemm_k<0><<<dim3(C_/192, M_/128), 256>>>(xd, lin3_w, lin3_b, y3, C_, C2_, C_);
    // yg = LN(y3) * silu(z)
    lngate_k<<<(M_*32 + 255)/256, 256>>>(norm_g, norm_b);
    // out = yg @ out_w^T + out_b, stored NCHW   (tf32 TC)
    tgemm_k<2><<<dim3(C_/192, M_/128), 256>>>(yg, out_w, out_b, out, C_, C_, C_);
}

// round 5
// speedup vs baseline: 1.9496x; 1.5771x over previous
#include <cuda_runtime.h>
#include <cuda_bf16.h>
#include <cstdint>
#include <math.h>

#define B_   64
#define C_   192
#define C2_  384
#define HW_  3136            // 56*56
#define M_   (B_*HW_)        // 200704

// ---------------- scratch (device globals), all channel-major ---------------
__device__ float g_y0    [M_*C_];    // dwconv out  [C][B*HW]
__device__ float g_t1    [M_*C2_];   // lin1 out    [2C][B*HW]  (x | z planes)
__device__ float g_xc    [M_*C_];    // dct1 result [C][B*HW]
__device__ float g_otT   [M_*C_];    // outline transposed [C][B*HW]
__device__ float g_xd    [M_*C2_];   // dct2 result [2C][B*HW]
__device__ float g_y3    [M_*C_];    // lin3 out    [C][B*HW]
__device__ float g_yg    [M_*C_];    // LN*silu     [C][B*HW]
__device__ float g_femixT [HW_*C_];  // [C][HW]
__device__ float g_mult1T [HW_*C_];
__device__ float g_otmeanT[HW_*C_];
__device__ float g_xmeanT [HW_*C2_];
__device__ float g_skftT  [HW_*C2_];
__device__ float g_mult2T [HW_*C2_];
__device__ float g_cos  [HW_];       // cos[n][h]
__device__ float g_cosT [HW_];       // cos[h][n]
__device__ float g_cosP [HW_];       // doubly-permuted (mode-1 B operand)
__device__ float g_dval [HW_];       // wn^2+wm^2 at spatial p=n*56+m

// ------------------------------- init --------------------------------------
__device__ __forceinline__ float cosv(int n, int h){
    const float PI = 3.14159265358979323846f;
    float v = cosf((float)n * ((h + 0.5f)/56.0f) * PI) * sqrtf(2.0f/56.0f);
    if (n == 0) v *= 0.70710678118654752440f;
    return v;
}
__global__ void init_k(){
    int i = blockIdx.x*blockDim.x + threadIdx.x;
    if (i >= HW_) return;
    int a = i/56, b = i%56;
    g_cos [i] = cosv(a, b);
    g_cosT[i] = cosv(b, a);
    int ja = (a%28)*2 + a/28;     // permutation (self-inverse map)
    int jb = (b%28)*2 + b/28;
    g_cosP[i] = cosv(jb, ja);
    const float PI = 3.14159265358979323846f;
    float wn = PI*(float)a/56.0f, wm = PI*(float)b/56.0f;
    g_dval[i] = wn*wn + wm*wm;
}

// -------------------- depthwise 3x3 conv, plane -> plane -------------------
__global__ __launch_bounds__(256) void dwconv_k(const float* __restrict__ x,
        const float* __restrict__ wc, const float* __restrict__ bc){
    __shared__ float sp[58][58];
    int id = blockIdx.x;
    int c = id % C_, b = id / C_;
    const float* xp = x + ((size_t)b*C_ + c)*HW_;
    int t = threadIdx.x;
    for (int i = t; i < 58*58; i += 256) sp[i/58][i%58] = 0.f;
    __syncthreads();
    for (int i = t; i < HW_; i += 256) sp[i/56 + 1][i%56 + 1] = xp[i];
    float w[9];
    #pragma unroll
    for (int k = 0; k < 9; k++) w[k] = wc[c*9 + k];
    float bias = bc[c];
    __syncthreads();
    float* yp = g_y0 + (size_t)c*M_ + (size_t)b*HW_;
    for (int i = t; i < HW_; i += 256){
        int r = i/56, q = i%56;
        float a = bias;
        #pragma unroll
        for (int dy = 0; dy < 3; dy++)
            #pragma unroll
            for (int dx = 0; dx < 3; dx++)
                a += sp[r+dy][q+dx]*w[dy*3+dx];
        yp[i] = a;
    }
}

// ------------------- transpose outline NHWC -> otT cm ----------------------
__global__ __launch_bounds__(256) void transp_k(const float* __restrict__ in){
    __shared__ float tile[32][33];
    int c0 = blockIdx.x*32;          // 6 blocks
    int r0 = blockIdx.y*32;          // M_/32 blocks
    int lane = threadIdx.x & 31, w = threadIdx.x >> 5;
    #pragma unroll
    for (int i = w; i < 32; i += 8)
        tile[i][lane] = in[(size_t)(r0+i)*C_ + c0 + lane];
    __syncthreads();
    #pragma unroll
    for (int i = w; i < 32; i += 8)
        g_otT[(size_t)(c0+i)*M_ + r0 + lane] = tile[lane][i];
}

// ---------- otmeanT = mean_b(otT); femixT = otmeanT + freq_embed^T ---------
__global__ void otfemix_k(const float* __restrict__ fe){
    int i4 = blockIdx.x*blockDim.x + threadIdx.x;   // float4 over [C][HW]
    if (i4 >= HW_*C_/4) return;
    int c = i4 / (HW_/4), p4 = i4 - c*(HW_/4);
    const float* base = g_otT + (size_t)c*M_ + p4*4;
    float4 s = make_float4(0,0,0,0);
    #pragma unroll 8
    for (int b = 0; b < B_; b++){
        float4 v = *(const float4*)(base + (size_t)b*HW_);
        s.x += v.x; s.y += v.y; s.z += v.z; s.w += v.w;
    }
    const float inv = 1.0f/B_;
    float4 m = make_float4(s.x*inv, s.y*inv, s.z*inv, s.w*inv);
    ((float4*)g_otmeanT)[i4] = m;
    int p = p4*4;
    float4 f = make_float4(fe[(size_t)(p+0)*C_ + c], fe[(size_t)(p+1)*C_ + c],
                           fe[(size_t)(p+2)*C_ + c], fe[(size_t)(p+3)*C_ + c]);
    ((float4*)g_femixT)[i4] = make_float4(m.x+f.x, m.y+f.y, m.z+f.z, m.w+f.w);
}

// ----- xmeanT[c2][p]: c2<C from mean_b(xc); c2>=C copy otmeanT --------------
__global__ void xmean_k(){
    int i4 = blockIdx.x*blockDim.x + threadIdx.x;   // float4 over [2C][HW]
    if (i4 >= HW_*C2_/4) return;
    int c2 = i4 / (HW_/4), p4 = i4 - c2*(HW_/4);
    if (c2 < C_){
        const float* base = g_xc + (size_t)c2*M_ + p4*4;
        float4 s = make_float4(0,0,0,0);
        #pragma unroll 8
        for (int b = 0; b < B_; b++){
            float4 v = *(const float4*)(base + (size_t)b*HW_);
            s.x += v.x; s.y += v.y; s.z += v.z; s.w += v.w;
        }
        const float inv = 1.0f/B_;
        ((float4*)g_xmeanT)[i4] = make_float4(s.x*inv, s.y*inv, s.z*inv, s.w*inv);
    } else {
        ((float4*)g_xmeanT)[i4] = ((const float4*)g_otmeanT)[(size_t)(c2-C_)*(HW_/4) + p4];
    }
}

// ---------------- SIMT NN GEMM on channel-major small tensors --------------
// Cout[m][n] = sum_k W[m][k] * X[k][n] + bias[m];  n stride = N (=HW_)
// EPI 0: plain.  EPI 1: exp(-relu(v)*dval[n]).
template<int EPI>
__global__ __launch_bounds__(256) void cmgemm_k(
        const float* __restrict__ W, const float* __restrict__ X,
        const float* __restrict__ bias, float* __restrict__ Cout,
        int M, int N, int K)
{
    __shared__ float As[16][68];
    __shared__ float Bs[16][68];
    int t = threadIdx.x;
    int m0 = blockIdx.y*64, n0 = blockIdx.x*64;
    int ty = t >> 4, tx = t & 15;
    float acc[4][4];
    #pragma unroll
    for (int i = 0; i < 4; i++){ acc[i][0]=0;acc[i][1]=0;acc[i][2]=0;acc[i][3]=0; }

    int am = t >> 2, akk = (t & 3)*4;
    int bk = t >> 4, bf = (t & 15)*4;

    for (int k0 = 0; k0 < K; k0 += 16){
        float4 wa = *(const float4*)&W[(size_t)(m0+am)*K + k0 + akk];
        float4 xb = *(const float4*)&X[(size_t)(k0+bk)*N + n0 + bf];
        __syncthreads();
        As[akk+0][am] = wa.x; As[akk+1][am] = wa.y;
        As[akk+2][am] = wa.z; As[akk+3][am] = wa.w;
        *(float4*)&Bs[bk][bf] = xb;
        __syncthreads();
        #pragma unroll
        for (int k = 0; k < 16; k++){
            float a[4], b[4];
            #pragma unroll
            for (int i = 0; i < 4; i++) a[i] = As[k][ty*4+i];
            #pragma unroll
            for (int j = 0; j < 4; j++) b[j] = Bs[k][tx*4+j];
            #pragma unroll
            for (int i = 0; i < 4; i++)
                #pragma unroll
                for (int j = 0; j < 4; j++) acc[i][j] += a[i]*b[j];
        }
    }
    #pragma unroll
    for (int i = 0; i < 4; i++){
        int m = m0 + ty*4 + i;
        float bm = bias[m];
        float4 v;
        float* vp = &v.x;
        #pragma unroll
        for (int j = 0; j < 4; j++){
            float u = acc[i][j] + bm;
            if (EPI == 1){
                u = fmaxf(u, 0.f);
                u = expf(-u * g_dval[n0 + tx*4 + j]);
            }
            vp[j] = u;
        }
        *(float4*)&Cout[(size_t)m*N + n0 + tx*4] = v;
    }
}

// ------------------------ tf32 tensor-core NN GEMM -------------------------
// Rows = bp (Ntot=M_), cols = output channels. C[cc][bp] = sum_k W[cc][k]*X[k][bp].
// BM=128 rows, BN=192 cols, BK=16. 8 warps (4x2), warp tile 32x96.
// EPI 0: Cout[cc*Ntot + bp] (channel-major). EPI 1: NCHW (out tensor, 192 ch).
__device__ __forceinline__ float to_tf32(float x){
    uint32_t u; asm("cvt.rna.tf32.f32 %0, %1;" : "=r"(u) : "f"(x));
    return __uint_as_float(u);
}
__device__ __forceinline__ void mma_tf32(float c[4], const uint32_t a[4], const uint32_t b[2]){
    asm volatile("mma.sync.aligned.m16n8k8.row.col.f32.tf32.tf32.f32 "
        "{%0,%1,%2,%3}, {%4,%5,%6,%7}, {%8,%9}, {%0,%1,%2,%3};"
        : "+f"(c[0]), "+f"(c[1]), "+f"(c[2]), "+f"(c[3])
        : "r"(a[0]), "r"(a[1]), "r"(a[2]), "r"(a[3]), "r"(b[0]), "r"(b[1]));
}

template<int EPI>
__global__ __launch_bounds__(256) void tgemm_k(
        const float* __restrict__ X, const float* __restrict__ Wm,
        const float* __restrict__ bias, float* __restrict__ Cout,
        int K)
{
    __shared__ float As[2][16][136];
    __shared__ float Bs[2][16][200];
    const int t = threadIdx.x;
    const int lane = t & 31, warp = t >> 5;
    const int gid = lane >> 2, tig = lane & 3;
    const int wm = warp & 3, wn = warp >> 2;
    const int m0 = wm*32, n0 = wn*96;
    const int row0 = blockIdx.y*128, col0 = blockIdx.x*192;

    float acc[2][12][4];
    #pragma unroll
    for (int mt = 0; mt < 2; mt++)
        #pragma unroll
        for (int nt = 0; nt < 12; nt++)
            #pragma unroll
            for (int q = 0; q < 4; q++) acc[mt][nt][q] = 0.f;

    // A: X[k][bp] rows coalesced. thread loads k=ak and k=ak+8, float4 at af4.
    const int af4 = t & 31, ak = t >> 5;
    const float* Ag = X + (size_t)ak*M_ + row0 + af4*4;
    // B: W[col][k] K-contig (unchanged from NT form)
    int   brow[3], bk[3];
    const float* Bg[3];
    #pragma unroll
    for (int r = 0; r < 3; r++){
        int idx = t + r*256;
        brow[r] = idx >> 2; bk[r] = (idx & 3)*4;
        Bg[r] = Wm + (size_t)(col0 + brow[r])*K + bk[r];
    }

    float4 pa0, pa1, pb[3];
    pa0 = *(const float4*)(Ag);
    pa1 = *(const float4*)(Ag + (size_t)8*M_);
    #pragma unroll
    for (int r = 0; r < 3; r++) pb[r] = *(const float4*)(Bg[r]);

    {
        float4 q0 = make_float4(to_tf32(pa0.x),to_tf32(pa0.y),to_tf32(pa0.z),to_tf32(pa0.w));
        float4 q1 = make_float4(to_tf32(pa1.x),to_tf32(pa1.y),to_tf32(pa1.z),to_tf32(pa1.w));
        *(float4*)&As[0][ak  ][af4*4] = q0;
        *(float4*)&As[0][ak+8][af4*4] = q1;
        #pragma unroll
        for (int r = 0; r < 3; r++){
            Bs[0][bk[r]+0][brow[r]] = to_tf32(pb[r].x);
            Bs[0][bk[r]+1][brow[r]] = to_tf32(pb[r].y);
            Bs[0][bk[r]+2][brow[r]] = to_tf32(pb[r].z);
            Bs[0][bk[r]+3][brow[r]] = to_tf32(pb[r].w);
        }
    }
    __syncthreads();

    const int nIter = K >> 4;
    int s = 0;
    for (int it = 0; it < nIter; it++){
        if (it + 1 < nIter){
            int k0 = (it+1) << 4;
            pa0 = *(const float4*)(Ag + (size_t)k0*M_);
            pa1 = *(const float4*)(Ag + (size_t)(k0+8)*M_);
            #pragma unroll
            for (int r = 0; r < 3; r++) pb[r] = *(const float4*)(Bg[r] + k0);
        }
        #pragma unroll
        for (int ks = 0; ks < 16; ks += 8){
            uint32_t af[2][4];
            #pragma unroll
            for (int mt = 0; mt < 2; mt++){
                int mm = m0 + mt*16 + gid;
                af[mt][0] = __float_as_uint(As[s][ks+tig  ][mm]);
                af[mt][1] = __float_as_uint(As[s][ks+tig  ][mm+8]);
                af[mt][2] = __float_as_uint(As[s][ks+tig+4][mm]);
                af[mt][3] = __float_as_uint(As[s][ks+tig+4][mm+8]);
            }
            uint32_t bf[12][2];
            #pragma unroll
            for (int nt = 0; nt < 12; nt++){
                int nn = n0 + nt*8 + gid;
                bf[nt][0] = __float_as_uint(Bs[s][ks+tig  ][nn]);
                bf[nt][1] = __float_as_uint(Bs[s][ks+tig+4][nn]);
            }
            #pragma unroll
            for (int mt = 0; mt < 2; mt++)
                #pragma unroll
                for (int nt = 0; nt < 12; nt++)
                    mma_tf32(acc[mt][nt], af[mt], bf[nt]);
        }
        if (it + 1 < nIter){
            int sn = s ^ 1;
            float4 q0 = make_float4(to_tf32(pa0.x),to_tf32(pa0.y),to_tf32(pa0.z),to_tf32(pa0.w));
            float4 q1 = make_float4(to_tf32(pa1.x),to_tf32(pa1.y),to_tf32(pa1.z),to_tf32(pa1.w));
            *(float4*)&As[sn][ak  ][af4*4] = q0;
            *(float4*)&As[sn][ak+8][af4*4] = q1;
            #pragma unroll
            for (int r = 0; r < 3; r++){
                Bs[sn][bk[r]+0][brow[r]] = to_tf32(pb[r].x);
                Bs[sn][bk[r]+1][brow[r]] = to_tf32(pb[r].y);
                Bs[sn][bk[r]+2][brow[r]] = to_tf32(pb[r].z);
                Bs[sn][bk[r]+3][brow[r]] = to_tf32(pb[r].w);
            }
            __syncthreads();
            s = sn;
        }
    }

    #pragma unroll
    for (int mt = 0; mt < 2; mt++){
        #pragma unroll
        for (int nt = 0; nt < 12; nt++){
            int r0 = row0 + m0 + mt*16 + gid;
            int cc = col0 + n0 + nt*8 + tig*2;
            float b0v = bias[cc], b1v = bias[cc+1];
            float v00 = acc[mt][nt][0] + b0v, v01 = acc[mt][nt][1] + b1v;
            float v10 = acc[mt][nt][2] + b0v, v11 = acc[mt][nt][3] + b1v;
            if (EPI == 0){
                Cout[(size_t)cc    *M_ + r0    ] = v00;
                Cout[(size_t)(cc+1)*M_ + r0    ] = v01;
                Cout[(size_t)cc    *M_ + r0 + 8] = v10;
                Cout[(size_t)(cc+1)*M_ + r0 + 8] = v11;
            } else {
                int b0i = r0 / HW_,     p0i = r0 - b0i*HW_;
                int b1i = (r0+8) / HW_, p1i = (r0+8) - b1i*HW_;
                Cout[((size_t)(b0i*C_ + cc  ))*HW_ + p0i] = v00;
                Cout[((size_t)(b0i*C_ + cc+1))*HW_ + p0i] = v01;
                Cout[((size_t)(b1i*C_ + cc  ))*HW_ + p1i] = v10;
                Cout[((size_t)(b1i*C_ + cc+1))*HW_ + p1i] = v11;
            }
        }
    }
}

// ---------------- fused DCT2D * mult * IDCT2D per 56x56 plane --------------
// MODE 0: plane (b,c): in = inA plane, out = outA plane, mult = multT plane c.
// MODE 1: slice (b,s,c): even perm-cols from inA plane c, odd from inB plane c;
//         output/mult planes c (even) and c+192 (odd); positions 28s + u.
// Reference applies cos in the same orientation all 4 passes; mode-1 columns
// live in permuted space, handled by the pre-permuted table g_cosP.
template<int MODE>
__global__ __launch_bounds__(224) void dct_k(const float* __restrict__ inA,
                                             const float* __restrict__ inB,
                                             float* __restrict__ outA,
                                             const float* __restrict__ multT,
                                             const float* __restrict__ cosB)
{
    extern __shared__ float sh[];
    float* Sd = sh;              // [56][56]
    float* Td = sh + 3136;
    float* Cs = sh + 6272;       // cos[n][h]
    float* Cb = sh + 9408;       // B-operand table (cosT or cosP)
    const int t = threadIdx.x;
    const int id = blockIdx.x;

    int b, s = 0, c;
    if (MODE == 0){ b = id / C_; c = id - b*C_; }
    else { b = id / C2_; int rr = id - b*C2_; s = rr / C_; c = rr - s*C_; }

    const float* pinA = inA + (size_t)c*M_ + (size_t)b*HW_;
    const float* pinB = (MODE==1) ? inB + (size_t)c*M_ + (size_t)b*HW_ : nullptr;

    for (int f = t; f < 784; f += 224){
        ((float4*)Cs)[f] = ((const float4*)g_cos)[f];
        ((float4*)Cb)[f] = ((const float4*)cosB)[f];
        if (MODE == 0){
            ((float4*)Sd)[f] = ((const float4*)pinA)[f];
        } else {
            int r = f / 14, g4 = f - r*14;
            int par = g4 / 7, u = (g4 - par*7)*4;
            const float* src = par ? pinB : pinA;
            float4 v = *(const float4*)(src + r*56 + 28*s + u);
            *(float4*)&Sd[r*56 + par*28 + u] = v;
        }
    }
    __syncthreads();

    const bool act = (t < 196);
    int tr = 0, tc = 0;
    if (act){ tr = (t/14)*4; tc = (t - (t/14)*14)*4; }
    float acc[4][4];

    auto mm56 = [&](const float* Amat, const float* Bmat){
        #pragma unroll
        for (int i = 0; i < 4; i++){ acc[i][0]=0;acc[i][1]=0;acc[i][2]=0;acc[i][3]=0; }
        for (int k4 = 0; k4 < 56; k4 += 4){
            float av[4][4], bv[4][4];
            #pragma unroll
            for (int i = 0; i < 4; i++)
                *(float4*)av[i] = *(const float4*)&Amat[(tr+i)*56 + k4];
            #pragma unroll
            for (int kk = 0; kk < 4; kk++)
                *(float4*)bv[kk] = *(const float4*)&Bmat[(k4+kk)*56 + tc];
            #pragma unroll
            for (int kk = 0; kk < 4; kk++)
                #pragma unroll
                for (int i = 0; i < 4; i++)
                    #pragma unroll
                    for (int j = 0; j < 4; j++)
                        acc[i][j] += av[i][kk]*bv[kk][j];
        }
    };

    // MM1: Td = Cs x Sd
    if (act){
        mm56(Cs, Sd);
        #pragma unroll
        for (int i = 0; i < 4; i++) *(float4*)&Td[(tr+i)*56 + tc] = *(float4*)acc[i];
    }
    __syncthreads();
    // MM2: Sd = (Td x CsB) * mult
    if (act){
        mm56(Td, Cb);
        int par = (MODE==1) ? tc/28 : 0;
        const float* mp = multT + (size_t)(c + C_*par)*HW_;
        int mc = (MODE==1) ? (28*s + (tc - par*28)) : tc;
        #pragma unroll
        for (int i = 0; i < 4; i++){
            float4 mv = *(const float4*)&mp[(tr+i)*56 + mc];
            acc[i][0] *= mv.x; acc[i][1] *= mv.y; acc[i][2] *= mv.z; acc[i][3] *= mv.w;
            *(float4*)&Sd[(tr+i)*56 + tc] = *(float4*)acc[i];
        }
    }
    __syncthreads();
    // MM3: Td = Cs x Sd
    if (act){
        mm56(Cs, Sd);
        #pragma unroll
        for (int i = 0; i < 4; i++) *(float4*)&Td[(tr+i)*56 + tc] = *(float4*)acc[i];
    }
    __syncthreads();
    // MM4: out = Td x CsB
    if (act){
        mm56(Td, Cb);
        int par = (MODE==1) ? tc/28 : 0;
        float* op = outA + (size_t)(c + C_*par)*M_ + (size_t)b*HW_;
        int oc = (MODE==1) ? (28*s + (tc - par*28)) : tc;
        #pragma unroll
        for (int i = 0; i < 4; i++)
            *(float4*)&op[(tr+i)*56 + oc] = *(float4*)acc[i];
    }
}

// ----------------------- LayerNorm(y3) * silu(z), cm -----------------------
__global__ __launch_bounds__(256) void lngate_k(const float* __restrict__ gam,
                                                const float* __restrict__ bet)
{
    __shared__ float sy[C_][33];
    __shared__ float smu[32], srs[32];
    int bp0 = blockIdx.x*32;
    int lane = threadIdx.x & 31, w = threadIdx.x >> 5;
    #pragma unroll
    for (int i = w; i < C_; i += 8)
        sy[i][lane] = g_y3[(size_t)i*M_ + bp0 + lane];
    __syncthreads();
    // each warp reduces 4 p-columns
    #pragma unroll
    for (int q = 0; q < 4; q++){
        int p = w*4 + q;
        float sum = 0.f;
        #pragma unroll
        for (int k = 0; k < 6; k++) sum += sy[lane + 32*k][p];
        #pragma unroll
        for (int o = 16; o > 0; o >>= 1) sum += __shfl_xor_sync(0xffffffffu, sum, o);
        float mu = sum * (1.0f/C_);
        float qv = 0.f;
        #pragma unroll
        for (int k = 0; k < 6; k++){ float d = sy[lane + 32*k][p] - mu; qv += d*d; }
        #pragma unroll
        for (int o = 16; o > 0; o >>= 1) qv += __shfl_xor_sync(0xffffffffu, qv, o);
        if (lane == 0){ smu[p] = mu; srs[p] = rsqrtf(qv*(1.0f/C_) + 1e-5f); }
    }
    __syncthreads();
    #pragma unroll
    for (int i = w; i < C_; i += 8){
        float g = gam[i], bb = bet[i];
        float zz = g_t1[(size_t)(C_ + i)*M_ + bp0 + lane];
        float sil = zz / (1.0f + expf(-zz));
        g_yg[(size_t)i*M_ + bp0 + lane] =
            ((sy[i][lane] - smu[lane])*srs[lane]*g + bb) * sil;
    }
}

// --------------------------------- launch ----------------------------------
extern "C" void kernel_launch(void* const* d_in, const int* in_sizes, int n_in,
                              void* d_out, int out_size)
{
    const float* x        = (const float*)d_in[0];
    const float* fe       = (const float*)d_in[1];
    const float* ot       = (const float*)d_in[2];
    const float* dw_w     = (const float*)d_in[3];
    const float* dw_b     = (const float*)d_in[4];
    const float* lin_w    = (const float*)d_in[5];
    const float* lin_b    = (const float*)d_in[6];
    const float* tok_w    = (const float*)d_in[7];
    const float* tok_b    = (const float*)d_in[8];
    const float* lin2_w   = (const float*)d_in[9];
    const float* lin2_b   = (const float*)d_in[10];
    const float* tok2_w   = (const float*)d_in[11];
    const float* tok2_b   = (const float*)d_in[12];
    const float* lin3_w   = (const float*)d_in[13];
    const float* lin3_b   = (const float*)d_in[14];
    const float* norm_g   = (const float*)d_in[15];
    const float* norm_b   = (const float*)d_in[16];
    const float* out_w    = (const float*)d_in[17];
    const float* out_b    = (const float*)d_in[18];
    float* out = (float*)d_out;

    float *y0, *t1, *xc, *otT, *xd, *y3, *yg;
    float *femixT, *mult1T, *xmeanT, *skftT, *mult2T;
    float *cosT, *cosP;
    cudaGetSymbolAddress((void**)&y0,     g_y0);
    cudaGetSymbolAddress((void**)&t1,     g_t1);
    cudaGetSymbolAddress((void**)&xc,     g_xc);
    cudaGetSymbolAddress((void**)&otT,    g_otT);
    cudaGetSymbolAddress((void**)&xd,     g_xd);
    cudaGetSymbolAddress((void**)&y3,     g_y3);
    cudaGetSymbolAddress((void**)&yg,     g_yg);
    cudaGetSymbolAddress((void**)&femixT, g_femixT);
    cudaGetSymbolAddress((void**)&mult1T, g_mult1T);
    cudaGetSymbolAddress((void**)&xmeanT, g_xmeanT);
    cudaGetSymbolAddress((void**)&skftT,  g_skftT);
    cudaGetSymbolAddress((void**)&mult2T, g_mult2T);
    cudaGetSymbolAddress((void**)&cosT,   g_cosT);
    cudaGetSymbolAddress((void**)&cosP,   g_cosP);

    const int DCT_SMEM = 4*3136*4;   // 50176 B
    cudaFuncSetAttribute(dct_k<0>, cudaFuncAttributeMaxDynamicSharedMemorySize, DCT_SMEM);
    cudaFuncSetAttribute(dct_k<1>, cudaFuncAttributeMaxDynamicSharedMemorySize, DCT_SMEM);

    init_k<<<(HW_+255)/256, 256>>>();
    dwconv_k<<<B_*C_, 256>>>(x, dw_w, dw_b);
    transp_k<<<dim3(C_/32, M_/32), 256>>>(ot);
    otfemix_k<<<(HW_*C_/4 + 255)/256, 256>>>(fe);

    // mult1T = exp(-relu(tok_w @ femixT + b) * dval)
    cmgemm_k<1><<<dim3(HW_/64, C_/64), 256>>>(tok_w, femixT, tok_b, mult1T,
                                              C_, HW_, C_);
    // t1 = lin_w @ y0  (tf32, cm out)
    tgemm_k<0><<<dim3(C2_/192, M_/128), 256>>>(y0, lin_w, lin_b, t1, C_);
    // xc = dct-filter-idct (mode 0)
    dct_k<0><<<B_*C_, 224, DCT_SMEM>>>(t1, nullptr, xc, mult1T, cosT);

    xmean_k<<<(HW_*C2_/4 + 255)/256, 256>>>();
    // skftT = lin2 @ xmeanT + b
    cmgemm_k<0><<<dim3(HW_/64, C2_/64), 256>>>(lin2_w, xmeanT, lin2_b, skftT,
                                               C2_, HW_, C2_);
    // mult2T = exp(-relu(tok2 @ skftT + b) * dval)
    cmgemm_k<1><<<dim3(HW_/64, C2_/64), 256>>>(tok2_w, skftT, tok2_b, mult2T,
                                               C2_, HW_, C2_);
    // xd = interleaved dct-filter-idct (mode 1)
    dct_k<1><<<B_*C2_, 224, DCT_SMEM>>>(xc, otT, xd, mult2T, cosP);

    // y3 = lin3 @ xd  (tf32)
    tgemm_k<0><<<dim3(1, M_/128), 256>>>(xd, lin3_w, lin3_b, y3, C2_);
    // yg = LN(y3) * silu(z)
    lngate_k<<<M_/32, 256>>>(norm_g, norm_b);
    // out = out_w @ yg  (tf32, NCHW epilogue)
    tgemm_k<1><<<dim3(1, M_/128), 256>>>(yg, out_w, out_b, out, C_);
}